// round 5
// baseline (speedup 1.0000x reference)
#include <cuda_runtime.h>
#include <cstdint>

#define EMBED 768
#define HEAD 64
#define SEQ 4096
#define BATCH 4

// Scratch for Q, K, V projections: [B*T, 64] each, tf32-rounded fp32 bits.
// g_Q and g_K are stored with head-dim columns PERMUTED by
//   perm(c) = (c&~7) | ((c&3)<<1) | ((c>>2)&1)
// so that (k, k+4) mma-fragment pairs are adjacent words. S = Q.K^T is
// invariant under a shared contraction-dim permutation. g_V is unpermuted.
__device__ float g_Q[BATCH * SEQ * HEAD];
__device__ float g_K[BATCH * SEQ * HEAD];
__device__ float g_V[BATCH * SEQ * HEAD];

__device__ __forceinline__ uint32_t f2tf32(float x) {
    uint32_t r;
    asm("cvt.rna.tf32.f32 %0, %1;" : "=r"(r) : "f"(x));
    return r;
}

// D = A(16x8,row) * B(8x8,col) + D, tf32 inputs, f32 accum
__device__ __forceinline__ void mma_tf32(float c[4],
    uint32_t a0, uint32_t a1, uint32_t a2, uint32_t a3,
    uint32_t b0, uint32_t b1)
{
    asm volatile(
        "mma.sync.aligned.m16n8k8.row.col.f32.tf32.tf32.f32 "
        "{%0,%1,%2,%3}, {%4,%5,%6,%7}, {%8,%9}, {%0,%1,%2,%3};"
        : "+f"(c[0]), "+f"(c[1]), "+f"(c[2]), "+f"(c[3])
        : "r"(a0), "r"(a1), "r"(a2), "r"(a3), "r"(b0), "r"(b1));
}

__device__ __forceinline__ uint32_t s2u(const void* p) {
    uint32_t a;
    asm("{ .reg .u64 t; cvta.to.shared.u64 t, %1; cvt.u32.u64 %0, t; }"
        : "=r"(a) : "l"(p));
    return a;
}

#define CPA16(dst, src) \
    asm volatile("cp.async.cg.shared.global [%0], [%1], 16;" :: "r"(dst), "l"(src) : "memory")
#define CPA_COMMIT() asm volatile("cp.async.commit_group;" ::: "memory")
#define CPA_WAIT1()  asm volatile("cp.async.wait_group 1;" ::: "memory")
#define CPA_WAIT0()  asm volatile("cp.async.wait_group 0;" ::: "memory")

// ---------------------------------------------------------------------------
// QKV projection via tf32 mma. BM=128, 256 threads (8 warps), grid (128, 3).
// Q/K outputs written with permuted head columns; V written plain.
// ---------------------------------------------------------------------------
__global__ __launch_bounds__(256, 2) void qkv_kernel(
    const float* __restrict__ x,
    const float* __restrict__ Wq, const float* __restrict__ bq,
    const float* __restrict__ Wk, const float* __restrict__ bk,
    const float* __restrict__ Wv, const float* __restrict__ bv)
{
    extern __shared__ uint32_t dsm[];
    uint32_t* sx = dsm;                 // 128 x 68
    uint32_t* sw = dsm + 128 * 68;      // 64 x 72

    const float* __restrict__ W;
    const float* __restrict__ bias;
    float* out;
    if (blockIdx.y == 0)      { W = Wq; bias = bq; out = g_Q; }
    else if (blockIdx.y == 1) { W = Wk; bias = bk; out = g_K; }
    else                      { W = Wv; bias = bv; out = g_V; }

    const int t    = threadIdx.x;
    const int lane = t & 31;
    const int w16  = (t >> 5) << 4;
    const int gid  = lane >> 2;
    const int l3   = lane & 3;
    const int row0 = blockIdx.x * 128;

    float o[8][4];
#pragma unroll
    for (int n = 0; n < 8; n++)
#pragma unroll
        for (int c = 0; c < 4; c++) o[n][c] = 0.f;

    for (int e0 = 0; e0 < EMBED; e0 += 64) {
        __syncthreads();
#pragma unroll
        for (int i = 0; i < 8; i++) {
            int fi = t + i * 256;
            int r  = fi >> 4;
            int c  = (fi & 15) << 2;
            float4 xv = *(const float4*)&x[(size_t)(row0 + r) * EMBED + e0 + c];
            sx[r * 68 + c + 0] = f2tf32(xv.x);
            sx[r * 68 + c + 1] = f2tf32(xv.y);
            sx[r * 68 + c + 2] = f2tf32(xv.z);
            sx[r * 68 + c + 3] = f2tf32(xv.w);
        }
#pragma unroll
        for (int i = 0; i < 4; i++) {
            int fi = t + i * 256;
            int r  = fi >> 4;
            int c  = (fi & 15) << 2;
            float4 wv = *(const float4*)&W[(size_t)(e0 + r) * HEAD + c];
            sw[r * 72 + c + 0] = f2tf32(wv.x);
            sw[r * 72 + c + 1] = f2tf32(wv.y);
            sw[r * 72 + c + 2] = f2tf32(wv.z);
            sw[r * 72 + c + 3] = f2tf32(wv.w);
        }
        __syncthreads();

#pragma unroll
        for (int ks = 0; ks < 8; ks++) {
            int h = 8 * ks;
            uint32_t a0 = sx[(w16 + gid) * 68 + h + l3];
            uint32_t a1 = sx[(w16 + gid + 8) * 68 + h + l3];
            uint32_t a2 = sx[(w16 + gid) * 68 + h + l3 + 4];
            uint32_t a3 = sx[(w16 + gid + 8) * 68 + h + l3 + 4];
#pragma unroll
            for (int n = 0; n < 8; n++) {
                uint32_t b0 = sw[(h + l3) * 72 + 8 * n + gid];
                uint32_t b1 = sw[(h + l3 + 4) * 72 + 8 * n + gid];
                mma_tf32(o[n], a0, a1, a2, a3, b0, b1);
            }
        }
    }

    // q0/q1: permuted within-8-block positions of cols 2*l3 and 2*l3+1
    const int q0 = ((l3 & 1) << 2) | (l3 >> 1);   // 0,4,1,5
    const int q1 = q0 + 2;                        // 2,6,3,7
    size_t rowA = (size_t)(row0 + w16 + gid) * HEAD;
    size_t rowB = (size_t)(row0 + w16 + gid + 8) * HEAD;

#pragma unroll
    for (int n = 0; n < 8; n++) {
        int cb = 8 * n + 2 * l3;
        float b0 = bias[cb], b1 = bias[cb + 1];
        float v00 = __uint_as_float(f2tf32(o[n][0] + b0));
        float v01 = __uint_as_float(f2tf32(o[n][1] + b1));
        float v10 = __uint_as_float(f2tf32(o[n][2] + b0));
        float v11 = __uint_as_float(f2tf32(o[n][3] + b1));
        if (blockIdx.y < 2) {            // Q, K: permuted columns
            out[rowA + 8 * n + q0] = v00;
            out[rowA + 8 * n + q1] = v01;
            out[rowB + 8 * n + q0] = v10;
            out[rowB + 8 * n + q1] = v11;
        } else {                         // V: plain
            *(float2*)&out[rowA + cb] = make_float2(v00, v01);
            *(float2*)&out[rowB + cb] = make_float2(v10, v11);
        }
    }
}

// ---------------------------------------------------------------------------
// Flash attention, causal, tf32 mma, split-kn across 2 warp-groups.
// BM=64, 256 threads. Group g owns k-columns 32g..32g+31 of every kt tile.
// Q/K arrive pre-permuted -> all Q/K/P fragment loads are LDS.64.
// smem (words): sQ[0,4352) K[4352,13056) V[13056,22272) P[22272,26880)
// ---------------------------------------------------------------------------
__global__ __launch_bounds__(256, 2) void flash_kernel(float* __restrict__ out)
{
    extern __shared__ uint32_t smem[];
    const int SK = 4352, SV = 13056, SP = 22272;
    uint32_t* sQ = smem;

    const int b    = blockIdx.y;
    const int qt   = (int)gridDim.x - 1 - (int)blockIdx.x;  // heavy tiles first
    const int t    = threadIdx.x;
    const int lane = t & 31;
    const int warp = t >> 5;
    const int g    = warp >> 2;          // column-group 0/1
    const int w16  = (warp & 3) << 4;
    const int gid  = lane >> 2;
    const int l3   = lane & 3;
    const int r0   = w16 + gid;          // local q row (first of pair)
    const int l2   = 2 * l3;

    uint32_t* sPg = smem + SP + g * 2304;     // 64 x 36, group-private P (permuted cols)

    const float* __restrict__ Q = g_Q + (size_t)b * SEQ * HEAD;
    const float* __restrict__ K = g_K + (size_t)b * SEQ * HEAD;
    const float* __restrict__ V = g_V + (size_t)b * SEQ * HEAD;

    const uint32_t su = s2u(smem);

    // ---- prologue: async-load Q, K0/V0, K1/V1 ----
#pragma unroll
    for (int i = 0; i < 4; i++) {
        int id = t + i * 256;
        int r  = id >> 4;
        int c  = (id & 15) << 2;
        CPA16(su + (r * 68 + c) * 4, &Q[(size_t)(qt * 64 + r) * HEAD + c]);
        CPA16(su + (SK + r * 68 + c) * 4, &K[(size_t)(r) * HEAD + c]);
        CPA16(su + (SV + r * 72 + c) * 4, &V[(size_t)(r) * HEAD + c]);
    }
    CPA_COMMIT();
#pragma unroll
    for (int i = 0; i < 4; i++) {
        int id = t + i * 256;
        int r  = id >> 4;
        int c  = (id & 15) << 2;
        CPA16(su + (SK + 4352 + r * 68 + c) * 4, &K[(size_t)(64 + r) * HEAD + c]);
        CPA16(su + (SV + 4608 + r * 72 + c) * 4, &V[(size_t)(64 + r) * HEAD + c]);
    }
    CPA_COMMIT();

    float m0 = -1e30f, m1 = -1e30f, l0 = 0.f, l1 = 0.f;
    float o[8][4];
#pragma unroll
    for (int n = 0; n < 8; n++)
#pragma unroll
        for (int c = 0; c < 4; c++) o[n][c] = 0.f;

    for (int kt = 0; kt <= qt; kt++) {
        CPA_WAIT1();
        __syncthreads();

        const int st = kt & 1;
        uint32_t* sKc = smem + SK + st * 4352;
        uint32_t* sVc = smem + SV + st * 4608;

        // S_half = Q (16x64) . K_half(32x64)^T per warp  (paired LDS.64 frags)
        float s[4][4];
#pragma unroll
        for (int n = 0; n < 4; n++)
#pragma unroll
            for (int c = 0; c < 4; c++) s[n][c] = 0.f;

#pragma unroll
        for (int ks = 0; ks < 8; ks++) {
            int h2 = 8 * ks + l2;
            uint2 aA = *(const uint2*)&sQ[(r0) * 68 + h2];        // a0, a2
            uint2 aB = *(const uint2*)&sQ[(r0 + 8) * 68 + h2];    // a1, a3
#pragma unroll
            for (int n = 0; n < 4; n++) {
                int kr = 32 * g + 8 * n + gid;
                uint2 bb = *(const uint2*)&sKc[kr * 68 + h2];     // b0, b1
                mma_tf32(s[n], aA.x, aB.x, aA.y, aB.y, bb.x, bb.y);
            }
        }

        // Scale + causal mask (diagonal tile only)
        const float scale = 0.125f;
        if (kt == qt) {
#pragma unroll
            for (int n = 0; n < 4; n++) {
                int c0 = 32 * g + 8 * n + l2;
                s[n][0] = (c0     <= r0    ) ? s[n][0] * scale : -1e30f;
                s[n][1] = (c0 + 1 <= r0    ) ? s[n][1] * scale : -1e30f;
                s[n][2] = (c0     <= r0 + 8) ? s[n][2] * scale : -1e30f;
                s[n][3] = (c0 + 1 <= r0 + 8) ? s[n][3] * scale : -1e30f;
            }
        } else {
#pragma unroll
            for (int n = 0; n < 4; n++)
#pragma unroll
                for (int c = 0; c < 4; c++) s[n][c] *= scale;
        }

        // Online softmax over this group's 32 columns
        float mx0 = -1e30f, mx1 = -1e30f;
#pragma unroll
        for (int n = 0; n < 4; n++) {
            mx0 = fmaxf(mx0, fmaxf(s[n][0], s[n][1]));
            mx1 = fmaxf(mx1, fmaxf(s[n][2], s[n][3]));
        }
        mx0 = fmaxf(mx0, __shfl_xor_sync(0xffffffffu, mx0, 1));
        mx0 = fmaxf(mx0, __shfl_xor_sync(0xffffffffu, mx0, 2));
        mx1 = fmaxf(mx1, __shfl_xor_sync(0xffffffffu, mx1, 1));
        mx1 = fmaxf(mx1, __shfl_xor_sync(0xffffffffu, mx1, 2));

        float mn0 = fmaxf(m0, mx0);
        float mn1 = fmaxf(m1, mx1);
        float alpha0 = __expf(m0 - mn0);
        float alpha1 = __expf(m1 - mn1);
        m0 = mn0; m1 = mn1;

        float rs0 = 0.f, rs1 = 0.f;
#pragma unroll
        for (int n = 0; n < 4; n++) {
            s[n][0] = __expf(s[n][0] - mn0);
            s[n][1] = __expf(s[n][1] - mn0);
            s[n][2] = __expf(s[n][2] - mn1);
            s[n][3] = __expf(s[n][3] - mn1);
            rs0 += s[n][0] + s[n][1];
            rs1 += s[n][2] + s[n][3];
        }
        rs0 += __shfl_xor_sync(0xffffffffu, rs0, 1);
        rs0 += __shfl_xor_sync(0xffffffffu, rs0, 2);
        rs1 += __shfl_xor_sync(0xffffffffu, rs1, 1);
        rs1 += __shfl_xor_sync(0xffffffffu, rs1, 2);
        l0 = l0 * alpha0 + rs0;
        l1 = l1 * alpha1 + rs1;

#pragma unroll
        for (int n = 0; n < 8; n++) {
            o[n][0] *= alpha0; o[n][1] *= alpha0;
            o[n][2] *= alpha1; o[n][3] *= alpha1;
        }

        // Stage P with permuted local columns so consumer loads are LDS.64.
        // q0/q1 = permuted positions of within-block cols 2*l3, 2*l3+1.
        const int q0 = ((l3 & 1) << 2) | (l3 >> 1);
        const int q1 = q0 + 2;
#pragma unroll
        for (int n = 0; n < 4; n++) {
            sPg[(r0) * 36 + 8 * n + q0]     = f2tf32(s[n][0]);
            sPg[(r0) * 36 + 8 * n + q1]     = f2tf32(s[n][1]);
            sPg[(r0 + 8) * 36 + 8 * n + q0] = f2tf32(s[n][2]);
            sPg[(r0 + 8) * 36 + 8 * n + q1] = f2tf32(s[n][3]);
        }
        __syncwarp();

        // O += P_half(16x32) . V_half(32x64)
#pragma unroll
        for (int ks = 0; ks < 4; ks++) {
            int k0 = 8 * ks;
            uint2 pA = *(const uint2*)&sPg[(r0) * 36 + k0 + l2];      // a0, a2
            uint2 pB = *(const uint2*)&sPg[(r0 + 8) * 36 + k0 + l2];  // a1, a3
#pragma unroll
            for (int n = 0; n < 8; n++) {
                int vr = 32 * g + k0 + l3;
                uint32_t b0 = sVc[(vr) * 72 + 8 * n + gid];
                uint32_t b1 = sVc[(vr + 4) * 72 + 8 * n + gid];
                mma_tf32(o[n], pA.x, pB.x, pA.y, pB.y, b0, b1);
            }
        }

        __syncthreads();      // stage st fully consumed by all warps

        if (kt + 2 <= qt) {
#pragma unroll
            for (int i = 0; i < 4; i++) {
                int id = t + i * 256;
                int r  = id >> 4;
                int c  = (id & 15) << 2;
                CPA16(su + (SK + st * 4352 + r * 68 + c) * 4,
                      &K[(size_t)((kt + 2) * 64 + r) * HEAD + c]);
                CPA16(su + (SV + st * 4608 + r * 72 + c) * 4,
                      &V[(size_t)((kt + 2) * 64 + r) * HEAD + c]);
            }
        }
        CPA_COMMIT();
    }

    CPA_WAIT0();
    __syncthreads();

    // ---- Merge the two groups' partial (m, l, O) ----
    float* sML = (float*)(smem + SP);        // [2][64][2]
    if (l3 == 0) {
        sML[((g * 64 + r0)     << 1) + 0] = m0;
        sML[((g * 64 + r0)     << 1) + 1] = l0;
        sML[((g * 64 + r0 + 8) << 1) + 0] = m1;
        sML[((g * 64 + r0 + 8) << 1) + 1] = l1;
    }
    __syncthreads();
    const int og = 1 - g;
    float mo0 = sML[((og * 64 + r0)     << 1) + 0];
    float lo0 = sML[((og * 64 + r0)     << 1) + 1];
    float mo1 = sML[((og * 64 + r0 + 8) << 1) + 0];
    float lo1 = sML[((og * 64 + r0 + 8) << 1) + 1];

    float M0 = fmaxf(m0, mo0), M1 = fmaxf(m1, mo1);
    float sc0 = __expf(m0 - M0), sc1 = __expf(m1 - M1);
    float L0 = l0 * sc0 + lo0 * __expf(mo0 - M0);
    float L1 = l1 * sc1 + lo1 * __expf(mo1 - M1);

#pragma unroll
    for (int n = 0; n < 8; n++) {
        o[n][0] *= sc0; o[n][1] *= sc0;
        o[n][2] *= sc1; o[n][3] *= sc1;
    }

    float* sOB = (float*)smem;               // reuse sQ region, 64 x 68
    if (g == 1) {
#pragma unroll
        for (int n = 0; n < 8; n++) {
            int cb = 8 * n + l2;
            sOB[(r0) * 68 + cb + 0]     = o[n][0];
            sOB[(r0) * 68 + cb + 1]     = o[n][1];
            sOB[(r0 + 8) * 68 + cb + 0] = o[n][2];
            sOB[(r0 + 8) * 68 + cb + 1] = o[n][3];
        }
    }
    __syncthreads();
    if (g == 0) {
        float inv0 = 1.f / L0;
        float inv1 = 1.f / L1;
        size_t orow0 = (size_t)b * SEQ + qt * 64 + r0;
#pragma unroll
        for (int n = 0; n < 8; n++) {
            int cb = 8 * n + l2;
            float2 v0, v1;
            v0.x = (o[n][0] + sOB[(r0) * 68 + cb + 0])     * inv0;
            v0.y = (o[n][1] + sOB[(r0) * 68 + cb + 1])     * inv0;
            v1.x = (o[n][2] + sOB[(r0 + 8) * 68 + cb + 0]) * inv1;
            v1.y = (o[n][3] + sOB[(r0 + 8) * 68 + cb + 1]) * inv1;
            *(float2*)&out[orow0 * HEAD + cb]       = v0;
            *(float2*)&out[(orow0 + 8) * HEAD + cb] = v1;
        }
    }
}

extern "C" void kernel_launch(void* const* d_in, const int* in_sizes, int n_in,
                              void* d_out, int out_size)
{
    const float* x  = (const float*)d_in[0];
    const float* Wq = (const float*)d_in[1];
    const float* bq = (const float*)d_in[2];
    const float* Wk = (const float*)d_in[3];
    const float* bk = (const float*)d_in[4];
    const float* Wv = (const float*)d_in[5];
    const float* bv = (const float*)d_in[6];
    float* out = (float*)d_out;

    const size_t QKV_SMEM = (size_t)(128 * 68 + 64 * 72) * sizeof(uint32_t);   // 53248
    cudaFuncSetAttribute(qkv_kernel, cudaFuncAttributeMaxDynamicSharedMemorySize,
                         (int)QKV_SMEM);
    qkv_kernel<<<dim3(SEQ * BATCH / 128, 3), 256, QKV_SMEM>>>(x, Wq, bq, Wk, bk, Wv, bv);

    const size_t FLASH_SMEM = (size_t)26880 * sizeof(uint32_t);   // 107520 B
    cudaFuncSetAttribute(flash_kernel, cudaFuncAttributeMaxDynamicSharedMemorySize,
                         (int)FLASH_SMEM);
    flash_kernel<<<dim3(SEQ / 64, BATCH), 256, FLASH_SMEM>>>(out);
}

// round 7
// speedup vs baseline: 1.7784x; 1.7784x over previous
#include <cuda_runtime.h>
#include <cuda_fp16.h>
#include <cstdint>

#define EMBED 768
#define HEAD 64
#define SEQ 4096
#define BATCH 4

// Projections, fp16. g_Qh/g_Kh: [B*T, 64] row-major. g_Vth: [B][64 head][4096 seq]
__device__ __half g_Qh[BATCH * SEQ * HEAD];
__device__ __half g_Kh[BATCH * SEQ * HEAD];
__device__ __half g_Vth[BATCH * HEAD * SEQ];

__device__ __forceinline__ uint32_t f2tf32(float x) {
    uint32_t r;
    asm("cvt.rna.tf32.f32 %0, %1;" : "=r"(r) : "f"(x));
    return r;
}

__device__ __forceinline__ uint32_t h2_to_u32(__half2 h) {
    union { __half2 h; uint32_t u; } cvt;
    cvt.h = h;
    return cvt.u;
}

// tf32: D(16x8) += A(16x8) * B(8x8)
__device__ __forceinline__ void mma_tf32(float c[4],
    uint32_t a0, uint32_t a1, uint32_t a2, uint32_t a3,
    uint32_t b0, uint32_t b1)
{
    asm volatile(
        "mma.sync.aligned.m16n8k8.row.col.f32.tf32.tf32.f32 "
        "{%0,%1,%2,%3}, {%4,%5,%6,%7}, {%8,%9}, {%0,%1,%2,%3};"
        : "+f"(c[0]), "+f"(c[1]), "+f"(c[2]), "+f"(c[3])
        : "r"(a0), "r"(a1), "r"(a2), "r"(a3), "r"(b0), "r"(b1));
}

// fp16: D(16x8,f32) += A(16x16,f16) * B(16x8,f16)
__device__ __forceinline__ void mma_f16(float c[4],
    uint32_t a0, uint32_t a1, uint32_t a2, uint32_t a3,
    uint32_t b0, uint32_t b1)
{
    asm volatile(
        "mma.sync.aligned.m16n8k16.row.col.f32.f16.f16.f32 "
        "{%0,%1,%2,%3}, {%4,%5,%6,%7}, {%8,%9}, {%0,%1,%2,%3};"
        : "+f"(c[0]), "+f"(c[1]), "+f"(c[2]), "+f"(c[3])
        : "r"(a0), "r"(a1), "r"(a2), "r"(a3), "r"(b0), "r"(b1));
}

__device__ __forceinline__ uint32_t s2u(const void* p) {
    uint32_t a;
    asm("{ .reg .u64 t; cvta.to.shared.u64 t, %1; cvt.u32.u64 %0, t; }"
        : "=r"(a) : "l"(p));
    return a;
}

#define CPA16(dst, src) \
    asm volatile("cp.async.cg.shared.global [%0], [%1], 16;" :: "r"(dst), "l"(src) : "memory")
#define CPA_COMMIT() asm volatile("cp.async.commit_group;" ::: "memory")
#define CPA_WAIT1()  asm volatile("cp.async.wait_group 1;" ::: "memory")
#define CPA_WAIT0()  asm volatile("cp.async.wait_group 0;" ::: "memory")

// ---------------------------------------------------------------------------
// QKV projection via tf32 mma. BM=128, 256 threads, grid (128, 3).
// Q/K written as half2 [seq][head]; V written transposed [head][seq].
// ---------------------------------------------------------------------------
__global__ __launch_bounds__(256, 2) void qkv_kernel(
    const float* __restrict__ x,
    const float* __restrict__ Wq, const float* __restrict__ bq,
    const float* __restrict__ Wk, const float* __restrict__ bk,
    const float* __restrict__ Wv, const float* __restrict__ bv)
{
    extern __shared__ uint32_t dsm[];
    uint32_t* sx = dsm;                 // 128 x 68
    uint32_t* sw = dsm + 128 * 68;      // 64 x 72

    const float* __restrict__ W;
    const float* __restrict__ bias;
    if (blockIdx.y == 0)      { W = Wq; bias = bq; }
    else if (blockIdx.y == 1) { W = Wk; bias = bk; }
    else                      { W = Wv; bias = bv; }

    const int t    = threadIdx.x;
    const int lane = t & 31;
    const int w16  = (t >> 5) << 4;
    const int gid  = lane >> 2;
    const int l3   = lane & 3;
    const int row0 = blockIdx.x * 128;

    float o[8][4];
#pragma unroll
    for (int n = 0; n < 8; n++)
#pragma unroll
        for (int c = 0; c < 4; c++) o[n][c] = 0.f;

    for (int e0 = 0; e0 < EMBED; e0 += 64) {
        __syncthreads();
#pragma unroll
        for (int i = 0; i < 8; i++) {
            int fi = t + i * 256;
            int r  = fi >> 4;
            int c  = (fi & 15) << 2;
            float4 xv = *(const float4*)&x[(size_t)(row0 + r) * EMBED + e0 + c];
            sx[r * 68 + c + 0] = f2tf32(xv.x);
            sx[r * 68 + c + 1] = f2tf32(xv.y);
            sx[r * 68 + c + 2] = f2tf32(xv.z);
            sx[r * 68 + c + 3] = f2tf32(xv.w);
        }
#pragma unroll
        for (int i = 0; i < 4; i++) {
            int fi = t + i * 256;
            int r  = fi >> 4;
            int c  = (fi & 15) << 2;
            float4 wv = *(const float4*)&W[(size_t)(e0 + r) * HEAD + c];
            sw[r * 72 + c + 0] = f2tf32(wv.x);
            sw[r * 72 + c + 1] = f2tf32(wv.y);
            sw[r * 72 + c + 2] = f2tf32(wv.z);
            sw[r * 72 + c + 3] = f2tf32(wv.w);
        }
        __syncthreads();

#pragma unroll
        for (int ks = 0; ks < 8; ks++) {
            int h = 8 * ks;
            uint32_t a0 = sx[(w16 + gid) * 68 + h + l3];
            uint32_t a1 = sx[(w16 + gid + 8) * 68 + h + l3];
            uint32_t a2 = sx[(w16 + gid) * 68 + h + l3 + 4];
            uint32_t a3 = sx[(w16 + gid + 8) * 68 + h + l3 + 4];
#pragma unroll
            for (int n = 0; n < 8; n++) {
                uint32_t b0 = sw[(h + l3) * 72 + 8 * n + gid];
                uint32_t b1 = sw[(h + l3 + 4) * 72 + 8 * n + gid];
                mma_tf32(o[n], a0, a1, a2, a3, b0, b1);
            }
        }
    }

    const int rowA = row0 + w16 + gid;
    const int rowB = rowA + 8;

    if (blockIdx.y < 2) {
        __half* outh = (blockIdx.y == 0) ? g_Qh : g_Kh;
#pragma unroll
        for (int n = 0; n < 8; n++) {
            int cb = 8 * n + 2 * l3;
            float b0 = bias[cb], b1 = bias[cb + 1];
            *(__half2*)&outh[(size_t)rowA * HEAD + cb] =
                __floats2half2_rn(o[n][0] + b0, o[n][1] + b1);
            *(__half2*)&outh[(size_t)rowB * HEAD + cb] =
                __floats2half2_rn(o[n][2] + b0, o[n][3] + b1);
        }
    } else {
        // V transposed: g_Vth[b][head][seq]
        const int bb   = row0 / SEQ;
        const int seqA = rowA - bb * SEQ;
        __half* vt = g_Vth + (size_t)bb * HEAD * SEQ;
#pragma unroll
        for (int n = 0; n < 8; n++) {
            int cb = 8 * n + 2 * l3;
            float b0 = bias[cb], b1 = bias[cb + 1];
            vt[(size_t)(cb)     * SEQ + seqA]     = __float2half_rn(o[n][0] + b0);
            vt[(size_t)(cb + 1) * SEQ + seqA]     = __float2half_rn(o[n][1] + b1);
            vt[(size_t)(cb)     * SEQ + seqA + 8] = __float2half_rn(o[n][2] + b0);
            vt[(size_t)(cb + 1) * SEQ + seqA + 8] = __float2half_rn(o[n][3] + b1);
        }
    }
}

// ---------------------------------------------------------------------------
// Flash attention, causal, fp16 m16n8k16, split-kn across 2 warp-groups.
// BM=64, 256 threads. Group g owns k-cols 32g..32g+31 of every kt tile.
// P stays in registers (C-frag == A-frag layout after half2 packing).
// smem bytes: Q[0,9216) K[9216,27648) x2 stages, Vt[27648,46080) x2 stages.
// Row stride 72 halves (144B) -> all fragment LDS.32 conflict-free.
// ---------------------------------------------------------------------------
__global__ __launch_bounds__(256, 2) void flash_kernel(float* __restrict__ out)
{
    extern __shared__ __align__(16) unsigned char smraw[];
    __half* sh = (__half*)smraw;
    __half* sQ = sh;                     // 64 x 72 halves

    const int b    = blockIdx.y;
    const int qt   = (int)gridDim.x - 1 - (int)blockIdx.x;  // heavy tiles first
    const int t    = threadIdx.x;
    const int lane = t & 31;
    const int warp = t >> 5;
    const int g    = warp >> 2;          // column-group 0/1
    const int w16  = (warp & 3) << 4;
    const int gid  = lane >> 2;
    const int l3   = lane & 3;
    const int r0   = w16 + gid;
    const int l2   = 2 * l3;

    const __half* __restrict__ Qg = g_Qh + (size_t)b * SEQ * HEAD;
    const __half* __restrict__ Kg = g_Kh + (size_t)b * SEQ * HEAD;
    const __half* __restrict__ Vg = g_Vth + (size_t)b * HEAD * SEQ;

    const uint32_t su = s2u(sh);

    // ---- prologue: Q + stage0(kt=0) ; stage1(kt=1) ----
#pragma unroll
    for (int i = 0; i < 2; i++) {
        int id = t + i * 256;
        int r  = id >> 3;
        int ch = id & 7;
        CPA16(su + r * 144 + 16 * ch, Qg + (size_t)(qt * 64 + r) * HEAD + 8 * ch);
        CPA16(su + 9216 + r * 144 + 16 * ch, Kg + (size_t)r * HEAD + 8 * ch);
        CPA16(su + 27648 + r * 144 + 16 * ch, Vg + (size_t)r * SEQ + 8 * ch);
    }
    CPA_COMMIT();
#pragma unroll
    for (int i = 0; i < 2; i++) {
        int id = t + i * 256;
        int r  = id >> 3;
        int ch = id & 7;
        CPA16(su + 9216 + 9216 + r * 144 + 16 * ch,
              Kg + (size_t)(64 + r) * HEAD + 8 * ch);
        CPA16(su + 27648 + 9216 + r * 144 + 16 * ch,
              Vg + (size_t)r * SEQ + 64 + 8 * ch);
    }
    CPA_COMMIT();

    float m0 = -1e30f, m1 = -1e30f, l0 = 0.f, l1 = 0.f;
    float o[8][4];
#pragma unroll
    for (int n = 0; n < 8; n++)
#pragma unroll
        for (int c = 0; c < 4; c++) o[n][c] = 0.f;

    for (int kt = 0; kt <= qt; kt++) {
        CPA_WAIT1();
        __syncthreads();

        const int st = kt & 1;
        const __half* sKc = sh + 4608 + st * 4608;    // halves
        const __half* sVc = sh + 13824 + st * 4608;

        // S_half = Q(16x64) . K_half(32x64)^T ; 4 x k16 steps
        float s[4][4];
#pragma unroll
        for (int n = 0; n < 4; n++)
#pragma unroll
            for (int c = 0; c < 4; c++) s[n][c] = 0.f;

#pragma unroll
        for (int ks = 0; ks < 4; ks++) {
            int k0 = 16 * ks;
            uint32_t a0 = *(const uint32_t*)&sQ[(r0) * 72 + k0 + l2];
            uint32_t a1 = *(const uint32_t*)&sQ[(r0 + 8) * 72 + k0 + l2];
            uint32_t a2 = *(const uint32_t*)&sQ[(r0) * 72 + k0 + l2 + 8];
            uint32_t a3 = *(const uint32_t*)&sQ[(r0 + 8) * 72 + k0 + l2 + 8];
#pragma unroll
            for (int n = 0; n < 4; n++) {
                int kr = 32 * g + 8 * n + gid;
                uint32_t b0 = *(const uint32_t*)&sKc[kr * 72 + k0 + l2];
                uint32_t b1 = *(const uint32_t*)&sKc[kr * 72 + k0 + l2 + 8];
                mma_f16(s[n], a0, a1, a2, a3, b0, b1);
            }
        }

        // Scale + causal mask (diagonal tile only)
        const float scale = 0.125f;
        if (kt == qt) {
#pragma unroll
            for (int n = 0; n < 4; n++) {
                int c0 = 32 * g + 8 * n + l2;
                s[n][0] = (c0     <= r0    ) ? s[n][0] * scale : -1e30f;
                s[n][1] = (c0 + 1 <= r0    ) ? s[n][1] * scale : -1e30f;
                s[n][2] = (c0     <= r0 + 8) ? s[n][2] * scale : -1e30f;
                s[n][3] = (c0 + 1 <= r0 + 8) ? s[n][3] * scale : -1e30f;
            }
        } else {
#pragma unroll
            for (int n = 0; n < 4; n++)
#pragma unroll
                for (int c = 0; c < 4; c++) s[n][c] *= scale;
        }

        // Online softmax over this group's 32 columns
        float mx0 = -1e30f, mx1 = -1e30f;
#pragma unroll
        for (int n = 0; n < 4; n++) {
            mx0 = fmaxf(mx0, fmaxf(s[n][0], s[n][1]));
            mx1 = fmaxf(mx1, fmaxf(s[n][2], s[n][3]));
        }
        mx0 = fmaxf(mx0, __shfl_xor_sync(0xffffffffu, mx0, 1));
        mx0 = fmaxf(mx0, __shfl_xor_sync(0xffffffffu, mx0, 2));
        mx1 = fmaxf(mx1, __shfl_xor_sync(0xffffffffu, mx1, 1));
        mx1 = fmaxf(mx1, __shfl_xor_sync(0xffffffffu, mx1, 2));

        float mn0 = fmaxf(m0, mx0);
        float mn1 = fmaxf(m1, mx1);
        float alpha0 = __expf(m0 - mn0);
        float alpha1 = __expf(m1 - mn1);
        m0 = mn0; m1 = mn1;

        float rs0 = 0.f, rs1 = 0.f;
#pragma unroll
        for (int n = 0; n < 4; n++) {
            s[n][0] = __expf(s[n][0] - mn0);
            s[n][1] = __expf(s[n][1] - mn0);
            s[n][2] = __expf(s[n][2] - mn1);
            s[n][3] = __expf(s[n][3] - mn1);
            rs0 += s[n][0] + s[n][1];
            rs1 += s[n][2] + s[n][3];
        }
        rs0 += __shfl_xor_sync(0xffffffffu, rs0, 1);
        rs0 += __shfl_xor_sync(0xffffffffu, rs0, 2);
        rs1 += __shfl_xor_sync(0xffffffffu, rs1, 1);
        rs1 += __shfl_xor_sync(0xffffffffu, rs1, 2);
        l0 = l0 * alpha0 + rs0;
        l1 = l1 * alpha1 + rs1;

#pragma unroll
        for (int n = 0; n < 8; n++) {
            o[n][0] *= alpha0; o[n][1] *= alpha0;
            o[n][2] *= alpha1; o[n][3] *= alpha1;
        }

        // Pack P into A-fragments directly (C-frag layout == A-frag layout)
        uint32_t p[8];
#pragma unroll
        for (int n = 0; n < 4; n++) {
            p[2 * n]     = h2_to_u32(__floats2half2_rn(s[n][0], s[n][1]));
            p[2 * n + 1] = h2_to_u32(__floats2half2_rn(s[n][2], s[n][3]));
        }

        // O += P_half(16x32) . V_half(32x64) ; 2 x k16 steps
#pragma unroll
        for (int ks = 0; ks < 2; ks++) {
            uint32_t a0 = p[4 * ks + 0];
            uint32_t a1 = p[4 * ks + 1];
            uint32_t a2 = p[4 * ks + 2];
            uint32_t a3 = p[4 * ks + 3];
            int kb = 32 * g + 16 * ks + l2;
#pragma unroll
            for (int n = 0; n < 8; n++) {
                int vr = 8 * n + gid;
                uint32_t b0 = *(const uint32_t*)&sVc[vr * 72 + kb];
                uint32_t b1 = *(const uint32_t*)&sVc[vr * 72 + kb + 8];
                mma_f16(o[n], a0, a1, a2, a3, b0, b1);
            }
        }

        __syncthreads();      // stage st fully consumed by all warps

        if (kt + 2 <= qt) {
#pragma unroll
            for (int i = 0; i < 2; i++) {
                int id = t + i * 256;
                int r  = id >> 3;
                int ch = id & 7;
                CPA16(su + 9216 + st * 9216 + r * 144 + 16 * ch,
                      Kg + (size_t)((kt + 2) * 64 + r) * HEAD + 8 * ch);
                CPA16(su + 27648 + st * 9216 + r * 144 + 16 * ch,
                      Vg + (size_t)r * SEQ + (kt + 2) * 64 + 8 * ch);
            }
        }
        CPA_COMMIT();
    }

    CPA_WAIT0();
    __syncthreads();

    // ---- Merge the two groups' partial (m, l, O) ----
    float* sML = (float*)smraw;              // [2][64][2] floats (Q region)
    if (l3 == 0) {
        sML[((g * 64 + r0)     << 1) + 0] = m0;
        sML[((g * 64 + r0)     << 1) + 1] = l0;
        sML[((g * 64 + r0 + 8) << 1) + 0] = m1;
        sML[((g * 64 + r0 + 8) << 1) + 1] = l1;
    }
    __syncthreads();
    const int og = 1 - g;
    float mo0 = sML[((og * 64 + r0)     << 1) + 0];
    float lo0 = sML[((og * 64 + r0)     << 1) + 1];
    float mo1 = sML[((og * 64 + r0 + 8) << 1) + 0];
    float lo1 = sML[((og * 64 + r0 + 8) << 1) + 1];

    float M0 = fmaxf(m0, mo0), M1 = fmaxf(m1, mo1);
    float sc0 = __expf(m0 - M0), sc1 = __expf(m1 - M1);
    float L0 = l0 * sc0 + lo0 * __expf(mo0 - M0);
    float L1 = l1 * sc1 + lo1 * __expf(mo1 - M1);

#pragma unroll
    for (int n = 0; n < 8; n++) {
        o[n][0] *= sc0; o[n][1] *= sc0;
        o[n][2] *= sc1; o[n][3] *= sc1;
    }

    float* sOB = (float*)(smraw + 9216);     // 64 x 68 floats (K region)
    if (g == 1) {
#pragma unroll
        for (int n = 0; n < 8; n++) {
            int cb = 8 * n + l2;
            sOB[(r0) * 68 + cb + 0]     = o[n][0];
            sOB[(r0) * 68 + cb + 1]     = o[n][1];
            sOB[(r0 + 8) * 68 + cb + 0] = o[n][2];
            sOB[(r0 + 8) * 68 + cb + 1] = o[n][3];
        }
    }
    __syncthreads();
    if (g == 0) {
        float inv0 = 1.f / L0;
        float inv1 = 1.f / L1;
        size_t orow0 = (size_t)b * SEQ + qt * 64 + r0;
#pragma unroll
        for (int n = 0; n < 8; n++) {
            int cb = 8 * n + l2;
            float2 v0, v1;
            v0.x = (o[n][0] + sOB[(r0) * 68 + cb + 0])     * inv0;
            v0.y = (o[n][1] + sOB[(r0) * 68 + cb + 1])     * inv0;
            v1.x = (o[n][2] + sOB[(r0 + 8) * 68 + cb + 0]) * inv1;
            v1.y = (o[n][3] + sOB[(r0 + 8) * 68 + cb + 1]) * inv1;
            *(float2*)&out[orow0 * HEAD + cb]       = v0;
            *(float2*)&out[(orow0 + 8) * HEAD + cb] = v1;
        }
    }
}

extern "C" void kernel_launch(void* const* d_in, const int* in_sizes, int n_in,
                              void* d_out, int out_size)
{
    const float* x  = (const float*)d_in[0];
    const float* Wq = (const float*)d_in[1];
    const float* bq = (const float*)d_in[2];
    const float* Wk = (const float*)d_in[3];
    const float* bk = (const float*)d_in[4];
    const float* Wv = (const float*)d_in[5];
    const float* bv = (const float*)d_in[6];
    float* out = (float*)d_out;

    const size_t QKV_SMEM = (size_t)(128 * 68 + 64 * 72) * sizeof(uint32_t);   // 53248
    cudaFuncSetAttribute(qkv_kernel, cudaFuncAttributeMaxDynamicSharedMemorySize,
                         (int)QKV_SMEM);
    qkv_kernel<<<dim3(SEQ * BATCH / 128, 3), 256, QKV_SMEM>>>(x, Wq, bq, Wk, bk, Wv, bv);

    const size_t FLASH_SMEM = 46080;         // bytes: Q 9216 + K 2x9216 + Vt 2x9216
    cudaFuncSetAttribute(flash_kernel, cudaFuncAttributeMaxDynamicSharedMemorySize,
                         (int)FLASH_SMEM);
    flash_kernel<<<dim3(SEQ / 64, BATCH), 256, FLASH_SMEM>>>(out);
}